// round 13
// baseline (speedup 1.0000x reference)
#include <cuda_runtime.h>
#include <cuda_fp16.h>

#define HEAD_DIM     128
#define NUM_SEQS     8
#define SEQ_LEN      512
#define Q_HEADS     16
#define TOTAL_TOKENS 4096
#define ROW_STRIDE   (Q_HEADS * HEAD_DIM)   // 2048 floats per token row

#define BM 128        // q rows per CTA (8 warps x 16 rows)
#define BN 32         // kv rows per tile
#define NT 256
#define LDR 132       // raw fp32 staging leading dim (floats)

// packed fp16x2 layouts
#define LDKH 72       // K/Q: per row, 64 pair-slots + pad (LDS.64 bank-verified)
#define LDVW 132      // V: [kc*4+qc][d] row stride in uint2 (word stride 264)
#define KH_SZ (BN * LDKH)        // 2304 words
#define VW_SZ (8 * LDVW * 2)     // 2112 words
#define QH_SZ (BM * LDKH)        // 9216 words

#define RAW_SZ (2 * BN * LDR)    // 8448 words
#define RAW0   0
#define QH0    RAW_SZ                    // 8448
#define KH0    (QH0 + QH_SZ)             // 17664 (single buffer)
#define VW0    (KH0 + KH_SZ)             // 19968 (single buffer)
#define SMEM_WORDS (VW0 + VW_SZ)         // 22080
#define SMEM_BYTES (SMEM_WORDS * 4)      // 88320  (x2 CTAs = 176.6KB)

// (1/sqrt(128)) * log2(e)
#define SCALE_LOG2E 0.12751744467105866f

__device__ __forceinline__ void cp16(float* dst_smem, const float* src) {
    unsigned sa = (unsigned)__cvta_generic_to_shared(dst_smem);
    asm volatile("cp.async.cg.shared.global [%0], [%1], 16;\n" :: "r"(sa), "l"(src));
}

__device__ __forceinline__ float ex2f(float x) {
    float y; asm("ex2.approx.f32 %0, %1;" : "=f"(y) : "f"(x)); return y;
}

// pack two fp32 -> fp16x2 (lo = first element)
__device__ __forceinline__ unsigned pk2(float lo, float hi) {
    unsigned d; asm("cvt.rn.f16x2.f32 %0, %1, %2;" : "=r"(d) : "f"(hi), "f"(lo)); return d;
}

// D += A(16x16 f16, row) * B(16x8 f16, col), fp32 accum
__device__ __forceinline__ void mma_f16(float* d, unsigned a0, unsigned a1,
                                        unsigned a2, unsigned a3,
                                        unsigned b0, unsigned b1) {
    asm volatile(
        "mma.sync.aligned.m16n8k16.row.col.f32.f16.f16.f32 "
        "{%0,%1,%2,%3}, {%4,%5,%6,%7}, {%8,%9}, {%0,%1,%2,%3};\n"
        : "+f"(d[0]), "+f"(d[1]), "+f"(d[2]), "+f"(d[3])
        : "r"(a0), "r"(a1), "r"(a2), "r"(a3), "r"(b0), "r"(b1));
}

__device__ __forceinline__ void load_kv_async(float* raw,
                                              const float* K, const float* V,
                                              int row0, int head, int tid) {
    #pragma unroll
    for (int i = 0; i < 4; i++) {
        int idx = tid + i * NT;
        int r = idx >> 5, c = idx & 31;
        int gr = row0 + r; if (gr >= TOTAL_TOKENS) gr = TOTAL_TOKENS - 1;
        cp16(raw + r * LDR + c * 4, K + (size_t)gr * ROW_STRIDE + head * HEAD_DIM + c * 4);
    }
    float* rawV = raw + BN * LDR;
    #pragma unroll
    for (int i = 0; i < 4; i++) {
        int idx = tid + i * NT;
        int r = idx >> 5, c = idx & 31;
        int gr = row0 + r; if (gr >= TOTAL_TOKENS) gr = TOTAL_TOKENS - 1;
        cp16(rawV + r * LDR + c * 4, V + (size_t)gr * ROW_STRIDE + head * HEAD_DIM + c * 4);
    }
}

__global__ void __launch_bounds__(NT, 2)
fa_kernel(const float* __restrict__ Q, const float* __restrict__ K,
          const float* __restrict__ V, const int* __restrict__ ntok,
          float* __restrict__ Out) {
    extern __shared__ float sm[];
    unsigned* smw = (unsigned*)sm;

    const int qb = blockIdx.x, h = blockIdx.y, s = blockIdx.z;

    // num_tokens dtype sniff: int64 LE positive lengths have high word == 0
    const int tstr = (ntok[1] == 0) ? 2 : 1;
    int seq_start = 0;
    for (int i = 0; i < s; i++) seq_start += ntok[i * tstr];
    const int seq_len = ntok[s * tstr];
    if (qb * BM >= seq_len) return;
    const int q0 = seq_start + qb * BM;

    const int tid = threadIdx.x;
    const int w = tid >> 5, lane = tid & 31;
    const int qr = lane >> 2;   // 0..7
    const int qc = lane & 3;    // 0..3

    // ---- stage Q (scaled) through raw smem, pack fp16 pairs into QH ----
    // slot perm per kc-group of 8 pairs: p<4 -> 2p ; p>=4 -> 2(p-4)+1
    unsigned* QH = smw + QH0;
    for (int ch = 0; ch < 2; ch++) {            // 64 rows per chunk
        for (int i = tid; i < 64 * 32; i += NT) {
            int r = i >> 5, c4 = i & 31;
            int gr = q0 + ch * 64 + r; if (gr >= TOTAL_TOKENS) gr = TOTAL_TOKENS - 1;
            float4 vv = *(const float4*)&Q[(size_t)gr * ROW_STRIDE + h * HEAD_DIM + c4 * 4];
            float* d = sm + r * LDR + c4 * 4;
            d[0] = vv.x * SCALE_LOG2E; d[1] = vv.y * SCALE_LOG2E;
            d[2] = vv.z * SCALE_LOG2E; d[3] = vv.w * SCALE_LOG2E;
        }
        __syncthreads();
        #pragma unroll
        for (int i = 0; i < 8; i++) {           // paired slots: r(64) x u(32)
            int idx = tid + i * NT;
            int r = idx >> 5, u = idx & 31;
            int kc = u >> 2, t = u & 3;
            int j1 = kc * 8 + t, j2 = j1 + 4;
            float2 pa_ = *(const float2*)(sm + r * LDR + 2 * j1);
            float2 pb_ = *(const float2*)(sm + r * LDR + 2 * j2);
            uint2 pv; pv.x = pk2(pa_.x, pa_.y); pv.y = pk2(pb_.x, pb_.y);
            *(uint2*)(QH + (ch * 64 + r) * LDKH + kc * 8 + 2 * t) = pv;
        }
        __syncthreads();
    }

    float o[16][4];
    #pragma unroll
    for (int nc = 0; nc < 16; nc++) { o[nc][0] = o[nc][1] = o[nc][2] = o[nc][3] = 0.f; }
    float m0 = -1e30f, m1 = -1e30f, l0 = 0.f, l1 = 0.f;

    const int nkv = (seq_len + BN - 1) / BN;

    load_kv_async(sm + RAW0, K, V, seq_start, h, tid);
    asm volatile("cp.async.commit_group;\n");

    const unsigned* qrow = QH + (w * 16 + qr) * LDKH + 2 * qc;
    unsigned* KH = smw + KH0;
    unsigned* VW = smw + VW0;

    for (int kb = 0; kb < nkv; kb++) {
        asm volatile("cp.async.wait_group 0;\n");
        __syncthreads();   // raw ready AND all warps done reading packed (prev tile)

        // ---- repack raw fp32 -> fp16x2 fragment layouts (paired STS.64) ----
        const float* rawK = sm + RAW0;
        const float* rawV = rawK + BN * LDR;
        #pragma unroll
        for (int i = 0; i < 4; i++) {           // K: n(32) x u(32) pair-slots
            int idx = tid + i * NT;
            int n = idx >> 5, u = idx & 31;
            int kc = u >> 2, t = u & 3;
            int j1 = kc * 8 + t, j2 = j1 + 4;
            float2 pa_ = *(const float2*)(rawK + n * LDR + 2 * j1);
            float2 pb_ = *(const float2*)(rawK + n * LDR + 2 * j2);
            uint2 pv; pv.x = pk2(pa_.x, pa_.y); pv.y = pk2(pb_.x, pb_.y);
            *(uint2*)(KH + n * LDKH + kc * 8 + 2 * t) = pv;
        }
        #pragma unroll
        for (int i = 0; i < 4; i++) {           // V: r(8) x d(128)
            int idx = tid + i * NT;
            int r = idx >> 7, d = idx & 127;
            int kc = r >> 2, qq = r & 3;
            int k0 = kc * 16 + 2 * qq;
            float v0 = rawV[(k0)     * LDR + d];
            float v1 = rawV[(k0 + 1) * LDR + d];
            float v2 = rawV[(k0 + 8) * LDR + d];
            float v3 = rawV[(k0 + 9) * LDR + d];
            uint2 pv; pv.x = pk2(v0, v1); pv.y = pk2(v2, v3);
            *(uint2*)(VW + (r * LDVW + d) * 2) = pv;
        }
        __syncthreads();

        // raw buffer is free: prefetch next tile under the MMA phase
        if (kb + 1 < nkv) {
            load_kv_async(sm + RAW0, K, V, seq_start + (kb + 1) * BN, h, tid);
            asm volatile("cp.async.commit_group;\n");
        }

        // ---- S = Q K^T (kc-outer: Q frags loaded once) ----
        float sfr[4][4];
        #pragma unroll
        for (int nc = 0; nc < 4; nc++)
            sfr[nc][0] = sfr[nc][1] = sfr[nc][2] = sfr[nc][3] = 0.f;
        #pragma unroll
        for (int kc = 0; kc < 8; kc++) {
            uint2 a02 = *(const uint2*)(qrow + kc * 8);
            uint2 a13 = *(const uint2*)(qrow + 8 * LDKH + kc * 8);
            #pragma unroll
            for (int nc = 0; nc < 4; nc++) {
                uint2 b2 = *(const uint2*)(KH + (nc * 8 + qr) * LDKH + kc * 8 + 2 * qc);
                mma_f16(sfr[nc], a02.x, a13.x, a02.y, a13.y, b2.x, b2.y);
            }
        }

        // mask tail (klen < BN)
        const int klen = min(BN, seq_len - kb * BN);
        if (klen < BN) {
            #pragma unroll
            for (int nc = 0; nc < 4; nc++) {
                int c0 = nc * 8 + 2 * qc;
                if (c0 >= klen)     { sfr[nc][0] = -1e30f; sfr[nc][2] = -1e30f; }
                if (c0 + 1 >= klen) { sfr[nc][1] = -1e30f; sfr[nc][3] = -1e30f; }
            }
        }

        // ---- online softmax (log2 domain) ----
        float mx0 = -1e30f, mx1 = -1e30f;
        #pragma unroll
        for (int nc = 0; nc < 4; nc++) {
            mx0 = fmaxf(mx0, fmaxf(sfr[nc][0], sfr[nc][1]));
            mx1 = fmaxf(mx1, fmaxf(sfr[nc][2], sfr[nc][3]));
        }
        mx0 = fmaxf(mx0, __shfl_xor_sync(0xffffffffu, mx0, 1));
        mx0 = fmaxf(mx0, __shfl_xor_sync(0xffffffffu, mx0, 2));
        mx1 = fmaxf(mx1, __shfl_xor_sync(0xffffffffu, mx1, 1));
        mx1 = fmaxf(mx1, __shfl_xor_sync(0xffffffffu, mx1, 2));
        const float mn0 = fmaxf(m0, mx0), mn1 = fmaxf(m1, mx1);
        const float f0 = ex2f(m0 - mn0), f1 = ex2f(m1 - mn1);
        m0 = mn0; m1 = mn1;

        float sum0 = 0.f, sum1 = 0.f;
        #pragma unroll
        for (int nc = 0; nc < 4; nc++) {
            sfr[nc][0] = ex2f(sfr[nc][0] - mn0);
            sfr[nc][1] = ex2f(sfr[nc][1] - mn0);
            sfr[nc][2] = ex2f(sfr[nc][2] - mn1);
            sfr[nc][3] = ex2f(sfr[nc][3] - mn1);
            sum0 += sfr[nc][0] + sfr[nc][1];
            sum1 += sfr[nc][2] + sfr[nc][3];
        }
        sum0 += __shfl_xor_sync(0xffffffffu, sum0, 1);
        sum0 += __shfl_xor_sync(0xffffffffu, sum0, 2);
        sum1 += __shfl_xor_sync(0xffffffffu, sum1, 1);
        sum1 += __shfl_xor_sync(0xffffffffu, sum1, 2);
        l0 = l0 * f0 + sum0;
        l1 = l1 * f1 + sum1;

        // skip O-rescale when no lane's max changed (f==1 exactly)
        if (!__all_sync(0xffffffffu, (f0 == 1.f) && (f1 == 1.f))) {
            #pragma unroll
            for (int nc = 0; nc < 16; nc++) {
                o[nc][0] *= f0; o[nc][1] *= f0; o[nc][2] *= f1; o[nc][3] *= f1;
            }
        }

        // ---- P: C-frag IS the k16 fp16 A-frag layout — just pack ----
        unsigned pa[2][4];
        #pragma unroll
        for (int kc = 0; kc < 2; kc++) {
            pa[kc][0] = pk2(sfr[2 * kc][0],     sfr[2 * kc][1]);
            pa[kc][1] = pk2(sfr[2 * kc][2],     sfr[2 * kc][3]);
            pa[kc][2] = pk2(sfr[2 * kc + 1][0], sfr[2 * kc + 1][1]);
            pa[kc][3] = pk2(sfr[2 * kc + 1][2], sfr[2 * kc + 1][3]);
        }

        // ---- O += P V (paired LDS.64 B-frags) ----
        const unsigned* vb = VW + (qc * LDVW + qr) * 2;
        #pragma unroll
        for (int nc = 0; nc < 16; nc++) {
            #pragma unroll
            for (int kc = 0; kc < 2; kc++) {
                uint2 b2 = *(const uint2*)(vb + (kc * 4 * LDVW + nc * 8) * 2);
                mma_f16(o[nc], pa[kc][0], pa[kc][1], pa[kc][2], pa[kc][3], b2.x, b2.y);
            }
        }
        // single packed buffer is safe: next iteration's barrier (all threads
        // past their MMAs) orders the repack overwrite.
    }

    // ---- epilogue: normalize by 1/l and store ----
    const float r0 = 1.f / l0, r1 = 1.f / l1;
    const int row0g = q0 + w * 16 + qr;
    const int row1g = row0g + 8;
    const int lim = seq_start + seq_len;
    #pragma unroll
    for (int nc = 0; nc < 16; nc++) {
        if (row0g < lim) {
            float2 val = make_float2(o[nc][0] * r0, o[nc][1] * r0);
            *(float2*)&Out[((size_t)h * TOTAL_TOKENS + row0g) * HEAD_DIM + nc * 8 + 2 * qc] = val;
        }
        if (row1g < lim) {
            float2 val = make_float2(o[nc][2] * r1, o[nc][3] * r1);
            *(float2*)&Out[((size_t)h * TOTAL_TOKENS + row1g) * HEAD_DIM + nc * 8 + 2 * qc] = val;
        }
    }
}

extern "C" void kernel_launch(void* const* d_in, const int* in_sizes, int n_in,
                              void* d_out, int out_size) {
    const float* Q = (const float*)d_in[0];
    const float* K = (const float*)d_in[1];
    const float* V = (const float*)d_in[2];
    const int* ntok = (const int*)d_in[3];
    float* Out = (float*)d_out;

    cudaFuncSetAttribute(fa_kernel,
                         cudaFuncAttributeMaxDynamicSharedMemorySize, SMEM_BYTES);

    dim3 grid(SEQ_LEN / BM, Q_HEADS, NUM_SEQS);   // 4 x 16 x 8 = 512 CTAs
    fa_kernel<<<grid, NT, SMEM_BYTES>>>(Q, K, V, ntok, Out);
}

// round 14
// speedup vs baseline: 1.0102x; 1.0102x over previous
#include <cuda_runtime.h>
#include <cuda_fp16.h>

#define HEAD_DIM     128
#define NUM_SEQS     8
#define SEQ_LEN      512
#define Q_HEADS     16
#define TOTAL_TOKENS 4096
#define ROW_STRIDE   (Q_HEADS * HEAD_DIM)   // 2048 floats per token row

#define BM 128        // q rows per CTA (8 warps x 16 rows)
#define BN 32         // kv rows per tile
#define NT 256
#define LDR 132       // raw fp32 staging leading dim (floats)

// packed fp16x2 layouts
#define LDKH 72       // K/Q: per row, 64 pair-slots + pad (LDS.64 bank-verified)
#define LDVW 132      // V: [kc*4+qc][d] row stride in uint2 (word stride 264)
#define KH_SZ (BN * LDKH)        // 2304 words
#define VW_SZ (8 * LDVW * 2)     // 2112 words
#define QH_SZ (BM * LDKH)        // 9216 words

#define RAW_SZ (2 * BN * LDR)    // 8448 words
#define RAW0   0
#define QH0    RAW_SZ                    // 8448
#define KH0    (QH0 + QH_SZ)             // 17664 (single buffer)
#define VW0    (KH0 + KH_SZ)             // 19968 (single buffer)
#define SMEM_WORDS (VW0 + VW_SZ)         // 22080
#define SMEM_BYTES (SMEM_WORDS * 4)      // 88320  (x2 CTAs = 176.6KB)

// (1/sqrt(128)) * log2(e)
#define SCALE_LOG2E 0.12751744467105866f

__device__ __forceinline__ void cp16(float* dst_smem, const float* src) {
    unsigned sa = (unsigned)__cvta_generic_to_shared(dst_smem);
    asm volatile("cp.async.cg.shared.global [%0], [%1], 16;\n" :: "r"(sa), "l"(src));
}

__device__ __forceinline__ float ex2f(float x) {
    float y; asm("ex2.approx.f32 %0, %1;" : "=f"(y) : "f"(x)); return y;
}

// pack two fp32 -> fp16x2 (lo = first element)
__device__ __forceinline__ unsigned pk2(float lo, float hi) {
    unsigned d; asm("cvt.rn.f16x2.f32 %0, %1, %2;" : "=r"(d) : "f"(hi), "f"(lo)); return d;
}

// D += A(16x16 f16, row) * B(16x8 f16, col), fp32 accum
__device__ __forceinline__ void mma_f16(float* d, unsigned a0, unsigned a1,
                                        unsigned a2, unsigned a3,
                                        unsigned b0, unsigned b1) {
    asm volatile(
        "mma.sync.aligned.m16n8k16.row.col.f32.f16.f16.f32 "
        "{%0,%1,%2,%3}, {%4,%5,%6,%7}, {%8,%9}, {%0,%1,%2,%3};\n"
        : "+f"(d[0]), "+f"(d[1]), "+f"(d[2]), "+f"(d[3])
        : "r"(a0), "r"(a1), "r"(a2), "r"(a3), "r"(b0), "r"(b1));
}

__device__ __forceinline__ void load_kv_async(float* raw,
                                              const float* K, const float* V,
                                              int row0, int head, int tid) {
    #pragma unroll
    for (int i = 0; i < 4; i++) {
        int idx = tid + i * NT;
        int r = idx >> 5, c = idx & 31;
        int gr = row0 + r; if (gr >= TOTAL_TOKENS) gr = TOTAL_TOKENS - 1;
        cp16(raw + r * LDR + c * 4, K + (size_t)gr * ROW_STRIDE + head * HEAD_DIM + c * 4);
    }
    float* rawV = raw + BN * LDR;
    #pragma unroll
    for (int i = 0; i < 4; i++) {
        int idx = tid + i * NT;
        int r = idx >> 5, c = idx & 31;
        int gr = row0 + r; if (gr >= TOTAL_TOKENS) gr = TOTAL_TOKENS - 1;
        cp16(rawV + r * LDR + c * 4, V + (size_t)gr * ROW_STRIDE + head * HEAD_DIM + c * 4);
    }
}

__global__ void __launch_bounds__(NT, 2)
fa_kernel(const float* __restrict__ Q, const float* __restrict__ K,
          const float* __restrict__ V, const int* __restrict__ ntok,
          float* __restrict__ Out) {
    extern __shared__ float sm[];
    unsigned* smw = (unsigned*)sm;

    const int qb = blockIdx.x, h = blockIdx.y, s = blockIdx.z;

    // num_tokens dtype sniff: int64 LE positive lengths have high word == 0
    const int tstr = (ntok[1] == 0) ? 2 : 1;
    int seq_start = 0;
    for (int i = 0; i < s; i++) seq_start += ntok[i * tstr];
    const int seq_len = ntok[s * tstr];
    if (qb * BM >= seq_len) return;
    const int q0 = seq_start + qb * BM;

    const int tid = threadIdx.x;
    const int w = tid >> 5, lane = tid & 31;
    const int qr = lane >> 2;   // 0..7
    const int qc = lane & 3;    // 0..3

    // ---- stage Q (scaled) through raw smem, pack fp16 pairs into QH ----
    // slot perm per kc-group of 8 pairs: p<4 -> 2p ; p>=4 -> 2(p-4)+1
    unsigned* QH = smw + QH0;
    for (int ch = 0; ch < 2; ch++) {            // 64 rows per chunk
        for (int i = tid; i < 64 * 32; i += NT) {
            int r = i >> 5, c4 = i & 31;
            int gr = q0 + ch * 64 + r; if (gr >= TOTAL_TOKENS) gr = TOTAL_TOKENS - 1;
            float4 vv = *(const float4*)&Q[(size_t)gr * ROW_STRIDE + h * HEAD_DIM + c4 * 4];
            float* d = sm + r * LDR + c4 * 4;
            d[0] = vv.x * SCALE_LOG2E; d[1] = vv.y * SCALE_LOG2E;
            d[2] = vv.z * SCALE_LOG2E; d[3] = vv.w * SCALE_LOG2E;
        }
        __syncthreads();
        #pragma unroll
        for (int i = 0; i < 8; i++) {           // paired slots: r(64) x u(32)
            int idx = tid + i * NT;
            int r = idx >> 5, u = idx & 31;
            int kc = u >> 2, t = u & 3;
            int j1 = kc * 8 + t, j2 = j1 + 4;
            float2 pa_ = *(const float2*)(sm + r * LDR + 2 * j1);
            float2 pb_ = *(const float2*)(sm + r * LDR + 2 * j2);
            uint2 pv; pv.x = pk2(pa_.x, pa_.y); pv.y = pk2(pb_.x, pb_.y);
            *(uint2*)(QH + (ch * 64 + r) * LDKH + kc * 8 + 2 * t) = pv;
        }
        __syncthreads();
    }

    float o[16][4];
    #pragma unroll
    for (int nc = 0; nc < 16; nc++) { o[nc][0] = o[nc][1] = o[nc][2] = o[nc][3] = 0.f; }
    float m0 = -1e30f, m1 = -1e30f, l0 = 0.f, l1 = 0.f;

    const int nkv = (seq_len + BN - 1) / BN;

    load_kv_async(sm + RAW0, K, V, seq_start, h, tid);
    asm volatile("cp.async.commit_group;\n");

    const unsigned* qrow = QH + (w * 16 + qr) * LDKH + 2 * qc;
    unsigned* KH = smw + KH0;
    unsigned* VW = smw + VW0;

    for (int kb = 0; kb < nkv; kb++) {
        asm volatile("cp.async.wait_group 0;\n");
        __syncthreads();   // raw ready AND all warps done reading packed (prev tile)

        // ---- repack raw fp32 -> fp16x2 fragment layouts (paired STS.64) ----
        const float* rawK = sm + RAW0;
        const float* rawV = rawK + BN * LDR;
        #pragma unroll
        for (int i = 0; i < 4; i++) {           // K: n(32) x u(32) pair-slots
            int idx = tid + i * NT;
            int n = idx >> 5, u = idx & 31;
            int kc = u >> 2, t = u & 3;
            int j1 = kc * 8 + t, j2 = j1 + 4;
            float2 pa_ = *(const float2*)(rawK + n * LDR + 2 * j1);
            float2 pb_ = *(const float2*)(rawK + n * LDR + 2 * j2);
            uint2 pv; pv.x = pk2(pa_.x, pa_.y); pv.y = pk2(pb_.x, pb_.y);
            *(uint2*)(KH + n * LDKH + kc * 8 + 2 * t) = pv;
        }
        #pragma unroll
        for (int i = 0; i < 4; i++) {           // V: r(8) x d(128)
            int idx = tid + i * NT;
            int r = idx >> 7, d = idx & 127;
            int kc = r >> 2, qq = r & 3;
            int k0 = kc * 16 + 2 * qq;
            float v0 = rawV[(k0)     * LDR + d];
            float v1 = rawV[(k0 + 1) * LDR + d];
            float v2 = rawV[(k0 + 8) * LDR + d];
            float v3 = rawV[(k0 + 9) * LDR + d];
            uint2 pv; pv.x = pk2(v0, v1); pv.y = pk2(v2, v3);
            *(uint2*)(VW + (r * LDVW + d) * 2) = pv;
        }
        __syncthreads();

        // raw buffer is free: prefetch next tile under the MMA phase
        if (kb + 1 < nkv) {
            load_kv_async(sm + RAW0, K, V, seq_start + (kb + 1) * BN, h, tid);
            asm volatile("cp.async.commit_group;\n");
        }

        // ---- S = Q K^T (kc-outer: Q frags loaded once) ----
        float sfr[4][4];
        #pragma unroll
        for (int nc = 0; nc < 4; nc++)
            sfr[nc][0] = sfr[nc][1] = sfr[nc][2] = sfr[nc][3] = 0.f;
        #pragma unroll
        for (int kc = 0; kc < 8; kc++) {
            uint2 a02 = *(const uint2*)(qrow + kc * 8);
            uint2 a13 = *(const uint2*)(qrow + 8 * LDKH + kc * 8);
            #pragma unroll
            for (int nc = 0; nc < 4; nc++) {
                uint2 b2 = *(const uint2*)(KH + (nc * 8 + qr) * LDKH + kc * 8 + 2 * qc);
                mma_f16(sfr[nc], a02.x, a13.x, a02.y, a13.y, b2.x, b2.y);
            }
        }

        // mask tail (klen < BN)
        const int klen = min(BN, seq_len - kb * BN);
        if (klen < BN) {
            #pragma unroll
            for (int nc = 0; nc < 4; nc++) {
                int c0 = nc * 8 + 2 * qc;
                if (c0 >= klen)     { sfr[nc][0] = -1e30f; sfr[nc][2] = -1e30f; }
                if (c0 + 1 >= klen) { sfr[nc][1] = -1e30f; sfr[nc][3] = -1e30f; }
            }
        }

        // ---- online softmax (log2 domain) ----
        float mx0 = -1e30f, mx1 = -1e30f;
        #pragma unroll
        for (int nc = 0; nc < 4; nc++) {
            mx0 = fmaxf(mx0, fmaxf(sfr[nc][0], sfr[nc][1]));
            mx1 = fmaxf(mx1, fmaxf(sfr[nc][2], sfr[nc][3]));
        }
        mx0 = fmaxf(mx0, __shfl_xor_sync(0xffffffffu, mx0, 1));
        mx0 = fmaxf(mx0, __shfl_xor_sync(0xffffffffu, mx0, 2));
        mx1 = fmaxf(mx1, __shfl_xor_sync(0xffffffffu, mx1, 1));
        mx1 = fmaxf(mx1, __shfl_xor_sync(0xffffffffu, mx1, 2));
        const float mn0 = fmaxf(m0, mx0), mn1 = fmaxf(m1, mx1);
        const float f0 = ex2f(m0 - mn0), f1 = ex2f(m1 - mn1);
        m0 = mn0; m1 = mn1;

        float sum0 = 0.f, sum1 = 0.f;
        #pragma unroll
        for (int nc = 0; nc < 4; nc++) {
            sfr[nc][0] = ex2f(sfr[nc][0] - mn0);
            sfr[nc][1] = ex2f(sfr[nc][1] - mn0);
            sfr[nc][2] = ex2f(sfr[nc][2] - mn1);
            sfr[nc][3] = ex2f(sfr[nc][3] - mn1);
            sum0 += sfr[nc][0] + sfr[nc][1];
            sum1 += sfr[nc][2] + sfr[nc][3];
        }
        sum0 += __shfl_xor_sync(0xffffffffu, sum0, 1);
        sum0 += __shfl_xor_sync(0xffffffffu, sum0, 2);
        sum1 += __shfl_xor_sync(0xffffffffu, sum1, 1);
        sum1 += __shfl_xor_sync(0xffffffffu, sum1, 2);
        l0 = l0 * f0 + sum0;
        l1 = l1 * f1 + sum1;

        // skip O-rescale when no lane's max changed (f==1 exactly)
        if (!__all_sync(0xffffffffu, (f0 == 1.f) && (f1 == 1.f))) {
            #pragma unroll
            for (int nc = 0; nc < 16; nc++) {
                o[nc][0] *= f0; o[nc][1] *= f0; o[nc][2] *= f1; o[nc][3] *= f1;
            }
        }

        // ---- P: C-frag IS the k16 fp16 A-frag layout — just pack ----
        unsigned pa[2][4];
        #pragma unroll
        for (int kc = 0; kc < 2; kc++) {
            pa[kc][0] = pk2(sfr[2 * kc][0],     sfr[2 * kc][1]);
            pa[kc][1] = pk2(sfr[2 * kc][2],     sfr[2 * kc][3]);
            pa[kc][2] = pk2(sfr[2 * kc + 1][0], sfr[2 * kc + 1][1]);
            pa[kc][3] = pk2(sfr[2 * kc + 1][2], sfr[2 * kc + 1][3]);
        }

        // ---- O += P V (paired LDS.64 B-frags) ----
        const unsigned* vb = VW + (qc * LDVW + qr) * 2;
        #pragma unroll
        for (int nc = 0; nc < 16; nc++) {
            #pragma unroll
            for (int kc = 0; kc < 2; kc++) {
                uint2 b2 = *(const uint2*)(vb + (kc * 4 * LDVW + nc * 8) * 2);
                mma_f16(o[nc], pa[kc][0], pa[kc][1], pa[kc][2], pa[kc][3], b2.x, b2.y);
            }
        }
        // single packed buffer is safe: next iteration's barrier (all threads
        // past their MMAs) orders the repack overwrite.
    }

    // ---- epilogue: normalize by 1/l and store ----
    const float r0 = 1.f / l0, r1 = 1.f / l1;
    const int row0g = q0 + w * 16 + qr;
    const int row1g = row0g + 8;
    const int lim = seq_start + seq_len;
    #pragma unroll
    for (int nc = 0; nc < 16; nc++) {
        if (row0g < lim) {
            float2 val = make_float2(o[nc][0] * r0, o[nc][1] * r0);
            *(float2*)&Out[((size_t)h * TOTAL_TOKENS + row0g) * HEAD_DIM + nc * 8 + 2 * qc] = val;
        }
        if (row1g < lim) {
            float2 val = make_float2(o[nc][2] * r1, o[nc][3] * r1);
            *(float2*)&Out[((size_t)h * TOTAL_TOKENS + row1g) * HEAD_DIM + nc * 8 + 2 * qc] = val;
        }
    }
}

extern "C" void kernel_launch(void* const* d_in, const int* in_sizes, int n_in,
                              void* d_out, int out_size) {
    const float* Q = (const float*)d_in[0];
    const float* K = (const float*)d_in[1];
    const float* V = (const float*)d_in[2];
    const int* ntok = (const int*)d_in[3];
    float* Out = (float*)d_out;

    cudaFuncSetAttribute(fa_kernel,
                         cudaFuncAttributeMaxDynamicSharedMemorySize, SMEM_BYTES);

    dim3 grid(SEQ_LEN / BM, Q_HEADS, NUM_SEQS);   // 4 x 16 x 8 = 512 CTAs
    fa_kernel<<<grid, NT, SMEM_BYTES>>>(Q, K, V, ntok, Out);
}